// round 1
// baseline (speedup 1.0000x reference)
#include <cuda_runtime.h>
#include <cuda_bf16.h>

// RipsLayer: output[t] = ||X[i_t] - X[j_t]|| for 16384 gathered index pairs.
// The reference's dense NxN distance matrix is never materialized — only the
// P*2 gathered entries are computed.
//
// Inputs (metadata order):
//   d_in[0] = X       float32 [N, 3]        (N = 8192, 24576 elems)
//   d_in[1] = indices int32   [P, 2, 2]     (P = 8192, 32768 elems)
// Output:
//   d_out   = dgm     float32 [P, 2]        (16384 elems)
//
// Flattened: element t of the output corresponds to indices[2t] = i,
// indices[2t+1] = j  ->  out[t] = sqrt(sum_k (X[i,k]-X[j,k])^2), D = 3.

__global__ void rips_gather_dist_kernel(const float* __restrict__ X,
                                        const int2* __restrict__ idx,
                                        float* __restrict__ out,
                                        int total) {
    int t = blockIdx.x * blockDim.x + threadIdx.x;
    if (t >= total) return;

    int2 ij = idx[t];            // (i, j) for this diagram entry
    int i3 = ij.x * 3;
    int j3 = ij.y * 3;

    float ax = __ldg(&X[i3 + 0]);
    float ay = __ldg(&X[i3 + 1]);
    float az = __ldg(&X[i3 + 2]);
    float bx = __ldg(&X[j3 + 0]);
    float by = __ldg(&X[j3 + 1]);
    float bz = __ldg(&X[j3 + 2]);

    float dx = ax - bx;
    float dy = ay - by;
    float dz = az - bz;

    out[t] = sqrtf(fmaf(dx, dx, fmaf(dy, dy, dz * dz)));
}

extern "C" void kernel_launch(void* const* d_in, const int* in_sizes, int n_in,
                              void* d_out, int out_size) {
    const float* X   = (const float*)d_in[0];
    const int2*  idx = (const int2*)d_in[1];   // [P*2] pairs of (i, j)
    float*       out = (float*)d_out;

    int total = out_size;                      // P * 2 = 16384
    int threads = 128;
    int blocks = (total + threads - 1) / threads;
    rips_gather_dist_kernel<<<blocks, threads>>>(X, idx, out, total);
}